// round 16
// baseline (speedup 1.0000x reference)
#include <cuda_runtime.h>
#include <math.h>

#define NPTS  2048
#define PAIRS 64
#define IVALS 16

// ---- scratch (no allocations allowed) --------------------------------------
// g_colmin holds ~bits(min d2) accumulated with atomicMax (identity 0 == BSS
// init). final_kernel decodes and resets to 0, re-arming for graph replays.
__device__ unsigned g_colmin[PAIRS * NPTS];
__device__ float    g_rowpart[PAIRS * 16];

// FFMA-imm add: d = a*1.0 + c (kept out of nvcc's FADD folder).
__device__ __forceinline__ float add_via_ffma_imm(float a, float c)
{
    float d;
    asm("fma.rn.f32 %0, %1, 0f3F800000, %2;" : "=f"(d) : "f"(a), "f"(c));
    return d;
}

// ---------------------------------------------------------------------------
// Kernel 1: bidirectional chamfer with fused in-block source transform
// (R15 champion, UNCHANGED).
// Block (nsplit, pair): owns source rows y[nsplit*128 .. +128) (transformed
// in-block), streams ALL 2048 target points in 16 chunks of 128.
//   c  = fma(yfx,xx, fma(yfy,xy, fma(yfz,xz, q2)))  // |y|^2 - 2 x.y
//   d2 = ffma_imm(x2, 1.0, c)
// rowmin (source side) completes in block -> g_rowpart.
// colmin (target side) -> shared reduce -> atomicMax of ~bits(d2).
// ---------------------------------------------------------------------------
__global__ void __launch_bounds__(256, 3) chamfer_kernel(
    const float* __restrict__ src,
    const float* __restrict__ tgt,
    const float* __restrict__ rot,
    const float* __restrict__ trn,
    const float* __restrict__ scl)
{
    const int pair   = blockIdx.y;
    const int nsplit = blockIdx.x;
    const int t  = threadIdx.x;
    const int tn = t >> 4;
    const int tm = t & 15;

    __shared__ float  s_m[12];
    __shared__ float4 s_yrow[128];
    __shared__ float4 s_x[2][128];
    __shared__ float  s_red[2][16][129];
    __shared__ float  s_sum[8];

    const float* tg = tgt + (size_t)(pair & 15) * NPTS * 3;

    if (t == 0) {
        float ax = rot[pair * 3 + 0], ay = rot[pair * 3 + 1], az = rot[pair * 3 + 2];
        float sx, cx, sy, cy, sz, cz;
        sincosf(ax, &sx, &cx);
        sincosf(ay, &sy, &cy);
        sincosf(az, &sz, &cz);
        const float s = scl[pair];
        s_m[0] = s * (cy * cz);                s_m[1] = s * (-cy * sz);               s_m[2] = s * sy;
        s_m[3] = s * (cx * sz + sx * sy * cz); s_m[4] = s * (cx * cz - sx * sy * sz); s_m[5] = s * (-sx * cy);
        s_m[6] = s * (sx * sz - cx * sy * cz); s_m[7] = s * (sx * cz + cx * sy * sz); s_m[8] = s * (cx * cy);
        s_m[9]  = s * trn[pair * 3 + 0];
        s_m[10] = s * trn[pair * 3 + 1];
        s_m[11] = s * trn[pair * 3 + 2];
    }
    if (t >= 128) {
        const int j = t - 128;
        const float xx = tg[j * 3 + 0];
        const float xy = tg[j * 3 + 1];
        const float xz = tg[j * 3 + 2];
        s_x[0][j] = make_float4(xx, xy, xz,
                                fmaf(xx, xx, fmaf(xy, xy, xz * xz)));
    }
    __syncthreads();

    if (t < 128) {
        const float* sp = src + ((size_t)pair * NPTS + nsplit * 128 + t) * 3;
        const float px = sp[0], py = sp[1], pz = sp[2];
        const float qx = fmaf(s_m[0], px, fmaf(s_m[1], py, fmaf(s_m[2], pz, s_m[9])));
        const float qy = fmaf(s_m[3], px, fmaf(s_m[4], py, fmaf(s_m[5], pz, s_m[10])));
        const float qz = fmaf(s_m[6], px, fmaf(s_m[7], py, fmaf(s_m[8], pz, s_m[11])));
        const float q2 = fmaf(qx, qx, fmaf(qy, qy, qz * qz));
        s_yrow[t] = make_float4(-2.0f * qx, -2.0f * qy, -2.0f * qz, q2);
    }
    __syncthreads();

    float4 yf[8];
#pragma unroll
    for (int i = 0; i < 8; i++) yf[i] = s_yrow[tn * 8 + i];

    unsigned* cmin = g_colmin + pair * NPTS;

    float rm[8];
#pragma unroll
    for (int i = 0; i < 8; i++) rm[i] = 3.4e38f;

    for (int c = 0; c < 16; c++) {
        float nx, ny, nz;
        if (c < 15 && t < 128) {
            const float* tp = tg + ((c + 1) * 128 + t) * 3;
            nx = tp[0]; ny = tp[1]; nz = tp[2];
        }

        const float4* xb = &s_x[c & 1][0];

        float cm[8];
#pragma unroll
        for (int j = 0; j < 8; j++) cm[j] = 3.4e38f;

#pragma unroll
        for (int jj = 0; jj < 8; jj++) {
            const float4 x = xb[tm + 16 * jj];
#pragma unroll
            for (int i = 0; i < 8; i++) {
                float cc = fmaf(yf[i].x, x.x,
                           fmaf(yf[i].y, x.y,
                           fmaf(yf[i].z, x.z, yf[i].w)));
                float d2 = add_via_ffma_imm(x.w, cc);
                rm[i]  = fminf(rm[i], d2);
                cm[jj] = fminf(cm[jj], d2);
            }
        }

#pragma unroll
        for (int jj = 0; jj < 8; jj++) s_red[c & 1][tn][tm + 16 * jj] = cm[jj];
        if (c < 15 && t < 128)
            s_x[(c + 1) & 1][t] = make_float4(nx, ny, nz,
                                              fmaf(nx, nx, fmaf(ny, ny, nz * nz)));
        __syncthreads();

        if (t < 128) {
            float v = s_red[c & 1][0][t];
#pragma unroll
            for (int k = 1; k < 16; k++) v = fminf(v, s_red[c & 1][k][t]);
            v = fmaxf(v, 0.0f);
            atomicMax(&cmin[c * 128 + t], ~__float_as_uint(v));
        }
    }

#pragma unroll
    for (int i = 0; i < 8; i++) s_red[0][tm][tn * 8 + i] = rm[i];
    __syncthreads();

    float total = 0.0f;
    if (t < 128) {
        float v = s_red[0][0][t];
#pragma unroll
        for (int k = 1; k < 16; k++) v = fminf(v, s_red[0][k][t]);
        total = v;
    }
#pragma unroll
    for (int off = 16; off > 0; off >>= 1)
        total += __shfl_down_sync(0xffffffffu, total, off);
    if ((t & 31) == 0) s_sum[t >> 5] = total;
    __syncthreads();
    if (t == 0) {
        g_rowpart[pair * 16 + nsplit] =
            s_sum[0] + s_sum[1] + s_sum[2] + s_sum[3] +
            s_sum[4] + s_sum[5] + s_sum[6] + s_sum[7];
    }
}

// ---------------------------------------------------------------------------
// Kernel 2: per-pair means + combine, LATENCY-OPTIMIZED.
// 1024 threads/block (2 colmin entries each -> 32 warps hide load latency),
// shuffle reductions, 2 barriers total. Decodes ~bits colmin and resets it
// to 0 (the atomicMax identity) so the next graph replay starts clean.
// ---------------------------------------------------------------------------
__global__ void __launch_bounds__(1024) final_kernel(float* __restrict__ out)
{
    const int pair = blockIdx.x;
    const int t    = threadIdx.x;
    const int lane = t & 31;
    const int w    = t >> 5;

    __shared__ float s_w[32];

    unsigned* p0 = &g_colmin[pair * NPTS + t];
    unsigned* p1 = p0 + 1024;
    unsigned u0 = *p0;
    unsigned u1 = *p1;
    *p0 = 0u;                              // re-arm for next replay
    *p1 = 0u;
    float local = __uint_as_float(~u0) + __uint_as_float(~u1);
    if (t < 16) local += g_rowpart[pair * 16 + t];

#pragma unroll
    for (int off = 16; off > 0; off >>= 1)
        local += __shfl_down_sync(0xffffffffu, local, off);
    if (lane == 0) s_w[w] = local;
    __syncthreads();

    if (w == 0) {
        float v = s_w[lane];
#pragma unroll
        for (int off = 16; off > 0; off >>= 1)
            v += __shfl_down_sync(0xffffffffu, v, off);
        if (lane == 0) out[pair] = v * (1.0f / 2048.0f);
    }
}

// ---------------------------------------------------------------------------
extern "C" void kernel_launch(void* const* d_in, const int* in_sizes, int n_in,
                              void* d_out, int out_size)
{
    const float* src = (const float*)d_in[0];   // [4,16,2048,3]
    const float* tgt = (const float*)d_in[1];   // [16,2048,3]
    const float* rot = (const float*)d_in[2];   // [4,16,3]
    const float* trn = (const float*)d_in[3];   // [4,16,3]
    const float* scl = (const float*)d_in[4];   // [4,16]
    (void)in_sizes; (void)n_in; (void)out_size;

    chamfer_kernel<<<dim3(16, PAIRS), 256>>>(src, tgt, rot, trn, scl);
    final_kernel<<<PAIRS, 1024>>>((float*)d_out);
}

// round 17
// speedup vs baseline: 1.0211x; 1.0211x over previous
#include <cuda_runtime.h>
#include <math.h>

#define NPTS  2048
#define PAIRS 64
#define IVALS 16

// ---- scratch (no allocations allowed) --------------------------------------
// g_colmin holds ~bits(min d2) accumulated with atomicMax (identity 0 == BSS
// init). final_kernel decodes and resets to 0, re-arming for graph replays.
__device__ unsigned g_colmin[PAIRS * NPTS];
__device__ float    g_rowpart[PAIRS * 16];

// FFMA-imm add: d = a*1.0 + c (kept out of nvcc's FADD folder).
__device__ __forceinline__ float add_via_ffma_imm(float a, float c)
{
    float d;
    asm("fma.rn.f32 %0, %1, 0f3F800000, %2;" : "=f"(d) : "f"(a), "f"(c));
    return d;
}

// ---------------------------------------------------------------------------
// Kernel 1: bidirectional chamfer with fused in-block source transform
// (R15 champion, UNCHANGED).
// Block (nsplit, pair): owns source rows y[nsplit*128 .. +128) (transformed
// in-block), streams ALL 2048 target points in 16 chunks of 128.
//   c  = fma(yfx,xx, fma(yfy,xy, fma(yfz,xz, q2)))  // |y|^2 - 2 x.y
//   d2 = ffma_imm(x2, 1.0, c)
// rowmin (source side) completes in block -> g_rowpart.
// colmin (target side) -> shared reduce -> atomicMax of ~bits(d2).
// ---------------------------------------------------------------------------
__global__ void __launch_bounds__(256, 3) chamfer_kernel(
    const float* __restrict__ src,
    const float* __restrict__ tgt,
    const float* __restrict__ rot,
    const float* __restrict__ trn,
    const float* __restrict__ scl)
{
    const int pair   = blockIdx.y;
    const int nsplit = blockIdx.x;
    const int t  = threadIdx.x;
    const int tn = t >> 4;
    const int tm = t & 15;

    __shared__ float  s_m[12];
    __shared__ float4 s_yrow[128];
    __shared__ float4 s_x[2][128];
    __shared__ float  s_red[2][16][129];
    __shared__ float  s_sum[8];

    const float* tg = tgt + (size_t)(pair & 15) * NPTS * 3;

    if (t == 0) {
        float ax = rot[pair * 3 + 0], ay = rot[pair * 3 + 1], az = rot[pair * 3 + 2];
        float sx, cx, sy, cy, sz, cz;
        sincosf(ax, &sx, &cx);
        sincosf(ay, &sy, &cy);
        sincosf(az, &sz, &cz);
        const float s = scl[pair];
        s_m[0] = s * (cy * cz);                s_m[1] = s * (-cy * sz);               s_m[2] = s * sy;
        s_m[3] = s * (cx * sz + sx * sy * cz); s_m[4] = s * (cx * cz - sx * sy * sz); s_m[5] = s * (-sx * cy);
        s_m[6] = s * (sx * sz - cx * sy * cz); s_m[7] = s * (sx * cz + cx * sy * sz); s_m[8] = s * (cx * cy);
        s_m[9]  = s * trn[pair * 3 + 0];
        s_m[10] = s * trn[pair * 3 + 1];
        s_m[11] = s * trn[pair * 3 + 2];
    }
    if (t >= 128) {
        const int j = t - 128;
        const float xx = tg[j * 3 + 0];
        const float xy = tg[j * 3 + 1];
        const float xz = tg[j * 3 + 2];
        s_x[0][j] = make_float4(xx, xy, xz,
                                fmaf(xx, xx, fmaf(xy, xy, xz * xz)));
    }
    __syncthreads();

    if (t < 128) {
        const float* sp = src + ((size_t)pair * NPTS + nsplit * 128 + t) * 3;
        const float px = sp[0], py = sp[1], pz = sp[2];
        const float qx = fmaf(s_m[0], px, fmaf(s_m[1], py, fmaf(s_m[2], pz, s_m[9])));
        const float qy = fmaf(s_m[3], px, fmaf(s_m[4], py, fmaf(s_m[5], pz, s_m[10])));
        const float qz = fmaf(s_m[6], px, fmaf(s_m[7], py, fmaf(s_m[8], pz, s_m[11])));
        const float q2 = fmaf(qx, qx, fmaf(qy, qy, qz * qz));
        s_yrow[t] = make_float4(-2.0f * qx, -2.0f * qy, -2.0f * qz, q2);
    }
    __syncthreads();

    float4 yf[8];
#pragma unroll
    for (int i = 0; i < 8; i++) yf[i] = s_yrow[tn * 8 + i];

    unsigned* cmin = g_colmin + pair * NPTS;

    float rm[8];
#pragma unroll
    for (int i = 0; i < 8; i++) rm[i] = 3.4e38f;

    for (int c = 0; c < 16; c++) {
        float nx, ny, nz;
        if (c < 15 && t < 128) {
            const float* tp = tg + ((c + 1) * 128 + t) * 3;
            nx = tp[0]; ny = tp[1]; nz = tp[2];
        }

        const float4* xb = &s_x[c & 1][0];

        float cm[8];
#pragma unroll
        for (int j = 0; j < 8; j++) cm[j] = 3.4e38f;

#pragma unroll
        for (int jj = 0; jj < 8; jj++) {
            const float4 x = xb[tm + 16 * jj];
#pragma unroll
            for (int i = 0; i < 8; i++) {
                float cc = fmaf(yf[i].x, x.x,
                           fmaf(yf[i].y, x.y,
                           fmaf(yf[i].z, x.z, yf[i].w)));
                float d2 = add_via_ffma_imm(x.w, cc);
                rm[i]  = fminf(rm[i], d2);
                cm[jj] = fminf(cm[jj], d2);
            }
        }

#pragma unroll
        for (int jj = 0; jj < 8; jj++) s_red[c & 1][tn][tm + 16 * jj] = cm[jj];
        if (c < 15 && t < 128)
            s_x[(c + 1) & 1][t] = make_float4(nx, ny, nz,
                                              fmaf(nx, nx, fmaf(ny, ny, nz * nz)));
        __syncthreads();

        if (t < 128) {
            float v = s_red[c & 1][0][t];
#pragma unroll
            for (int k = 1; k < 16; k++) v = fminf(v, s_red[c & 1][k][t]);
            v = fmaxf(v, 0.0f);
            atomicMax(&cmin[c * 128 + t], ~__float_as_uint(v));
        }
    }

#pragma unroll
    for (int i = 0; i < 8; i++) s_red[0][tm][tn * 8 + i] = rm[i];
    __syncthreads();

    float total = 0.0f;
    if (t < 128) {
        float v = s_red[0][0][t];
#pragma unroll
        for (int k = 1; k < 16; k++) v = fminf(v, s_red[0][k][t]);
        total = v;
    }
#pragma unroll
    for (int off = 16; off > 0; off >>= 1)
        total += __shfl_down_sync(0xffffffffu, total, off);
    if ((t & 31) == 0) s_sum[t >> 5] = total;
    __syncthreads();
    if (t == 0) {
        g_rowpart[pair * 16 + nsplit] =
            s_sum[0] + s_sum[1] + s_sum[2] + s_sum[3] +
            s_sum[4] + s_sum[5] + s_sum[6] + s_sum[7];
    }
}

// ---------------------------------------------------------------------------
// Kernel 2: per-pair means + combine. R15's measured-best shape (256 thr,
// 8 loads/thread) with the shared tree replaced by shuffle reduction:
// 1 barrier instead of 8. Decodes ~bits colmin and resets it to 0 (the
// atomicMax identity) so the next graph replay starts clean.
// ---------------------------------------------------------------------------
__global__ void __launch_bounds__(256) final_kernel(float* __restrict__ out)
{
    const int pair = blockIdx.x;
    const int t    = threadIdx.x;
    const int lane = t & 31;
    const int w    = t >> 5;

    __shared__ float s_w[8];

    float local = (t < 16) ? g_rowpart[pair * 16 + t] : 0.0f;
#pragma unroll
    for (int k = 0; k < 8; k++) {
        unsigned* p = &g_colmin[pair * NPTS + t + 256 * k];
        unsigned u = *p;
        *p = 0u;                            // re-arm for next replay
        local += __uint_as_float(~u);
    }

#pragma unroll
    for (int off = 16; off > 0; off >>= 1)
        local += __shfl_down_sync(0xffffffffu, local, off);
    if (lane == 0) s_w[w] = local;
    __syncthreads();

    if (w == 0 && lane < 8) {
        float v = s_w[lane];
        v += __shfl_down_sync(0x000000ffu, v, 4);
        v += __shfl_down_sync(0x000000ffu, v, 2);
        v += __shfl_down_sync(0x000000ffu, v, 1);
        if (lane == 0) out[pair] = v * (1.0f / 2048.0f);
    }
}

// ---------------------------------------------------------------------------
extern "C" void kernel_launch(void* const* d_in, const int* in_sizes, int n_in,
                              void* d_out, int out_size)
{
    const float* src = (const float*)d_in[0];   // [4,16,2048,3]
    const float* tgt = (const float*)d_in[1];   // [16,2048,3]
    const float* rot = (const float*)d_in[2];   // [4,16,3]
    const float* trn = (const float*)d_in[3];   // [4,16,3]
    const float* scl = (const float*)d_in[4];   // [4,16]
    (void)in_sizes; (void)n_in; (void)out_size;

    chamfer_kernel<<<dim3(16, PAIRS), 256>>>(src, tgt, rot, trn, scl);
    final_kernel<<<PAIRS, 256>>>((float*)d_out);
}